// round 7
// baseline (speedup 1.0000x reference)
#include <cuda_runtime.h>
#include <math.h>

// ---------------------------------------------------------------------------
// TropicalMLP: with temp=1, trop_linear(x;W,b) = log(exp(x) @ exp(W)^T) + b.
// R6: 128x128x(splitK) GEMM tiles, TM=TN=8 (1 B smem per FFMA, 2x crossbar
// headroom), split-K x4 (layers 1-2) / x8 (layer 3) to keep 128 CTAs.
// Partial-sum reduce + log + bias fused into the LN kernel / final3 kernel.
// ---------------------------------------------------------------------------

#define KDIM 512
#define MROWS 1024

__device__ float g_Ew1[512 * 512];
__device__ float g_Ew2[512 * 512];
__device__ float g_Ew3[256 * 512];
__device__ float g_bufA[1024 * 512];
__device__ float g_bufB[1024 * 512];
__device__ float g_P[4 * 1024 * 512];   // split-K partials (also 8*1024*256)

// ---------------------------------------------------------------------------
__global__ __launch_bounds__(256) void exp_all_kernel(
    const float* __restrict__ x,  float* __restrict__ ex,
    const float* __restrict__ w1, float* __restrict__ e1,
    const float* __restrict__ w2, float* __restrict__ e2,
    const float* __restrict__ w3, float* __restrict__ e3) {
    int i = blockIdx.x * 256 + threadIdx.x;  // float4 index
    const float* s; float* d; int off;
    if (i < 131072)      { s = x;  d = ex; off = i; }
    else if (i < 196608) { s = w1; d = e1; off = i - 131072; }
    else if (i < 262144) { s = w2; d = e2; off = i - 196608; }
    else                 { s = w3; d = e3; off = i - 262144; }
    float4 v = reinterpret_cast<const float4*>(s)[off];
    v.x = expf(v.x); v.y = expf(v.y); v.z = expf(v.z); v.w = expf(v.w);
    reinterpret_cast<float4*>(d)[off] = v;
}

// ---------------------------------------------------------------------------
template <int N>
__device__ __forceinline__ void ld_vec(const float* __restrict__ p, float* r) {
#pragma unroll
    for (int i = 0; i < N; i += 4) {
        float4 v = *(const float4*)(p + i);
        r[i] = v.x; r[i + 1] = v.y; r[i + 2] = v.z; r[i + 3] = v.w;
    }
}

// ---------------------------------------------------------------------------
// Split-K GEMM partial:  P[kz][m, n] = sum_{k in chunk kz} A[m,k]*Bw[n,k]
// 128x128 tile, 256 threads, TM=TN=8, BK=16, double-buffered smem+frags.
// Grid: (OUT/128, 1024/128, KDIM/KC).  No log/bias here (done in reducer).
// ---------------------------------------------------------------------------
template <int KC>
__global__ __launch_bounds__(256, 1) void gemm_sk(
    const float* __restrict__ A, const float* __restrict__ Bw,
    float* __restrict__ P, int OUT) {
    constexpr int BM = 128, BN = 128, BK = 16, TM = 8, TN = 8;
    constexpr int NX = BN / TN;        // 16
    constexpr int AF = BM * BK / 256;  // 8
    constexpr int NTILE = KC / BK;

    __shared__ float As[2][BK][BM];
    __shared__ float Bs[2][BK][BN];

    const int tid = threadIdx.x;
    const int tx = tid % NX;
    const int ty = tid / NX;
    const int bm = blockIdx.y * BM;
    const int bn = blockIdx.x * BN;
    const int kz = blockIdx.z;

    const int alr = tid % BM, alc = (tid / BM) * AF;   // alc in {0,8}
    const float* Ap = A + (bm + alr) * KDIM + kz * KC + alc;
    const float* Bp = Bw + (bn + alr) * KDIM + kz * KC + alc;

    float acc[TM][TN] = {};
    float ar[AF], br[AF];
    float af[2][TM], bf[2][TN];

    ld_vec<AF>(Ap, ar);
    ld_vec<AF>(Bp, br);
#pragma unroll
    for (int i = 0; i < AF; i++) As[0][alc + i][alr] = ar[i];
#pragma unroll
    for (int i = 0; i < AF; i++) Bs[0][alc + i][alr] = br[i];
    __syncthreads();

#pragma unroll 1
    for (int t = 0; t < NTILE; t++) {
        const int cur = t & 1, nxt = cur ^ 1;
        const bool more = (t + 1 < NTILE);

        if (more) {
            ld_vec<AF>(Ap + (t + 1) * BK, ar);
            ld_vec<AF>(Bp + (t + 1) * BK, br);
        }

        ld_vec<TM>(&As[cur][0][ty * TM], af[0]);
        ld_vec<TN>(&Bs[cur][0][tx * TN], bf[0]);
#pragma unroll
        for (int kk = 0; kk < BK; kk++) {
            const int c = kk & 1, n = c ^ 1;
            if (kk + 1 < BK) {
                ld_vec<TM>(&As[cur][kk + 1][ty * TM], af[n]);
                ld_vec<TN>(&Bs[cur][kk + 1][tx * TN], bf[n]);
            }
#pragma unroll
            for (int r = 0; r < TM; r++)
#pragma unroll
                for (int s = 0; s < TN; s++)
                    acc[r][s] = fmaf(af[c][r], bf[c][s], acc[r][s]);
        }

        if (more) {
#pragma unroll
            for (int i = 0; i < AF; i++) As[nxt][alc + i][alr] = ar[i];
#pragma unroll
            for (int i = 0; i < AF; i++) Bs[nxt][alc + i][alr] = br[i];
            __syncthreads();
        }
    }

    // raw partial-sum epilogue
    float* Pp = P + (size_t)kz * MROWS * OUT;
#pragma unroll
    for (int r = 0; r < TM; r++) {
        float* row = Pp + (bm + ty * TM + r) * OUT + bn + tx * TN;
        *(float4*)(row)     = make_float4(acc[r][0], acc[r][1], acc[r][2], acc[r][3]);
        *(float4*)(row + 4) = make_float4(acc[r][4], acc[r][5], acc[r][6], acc[r][7]);
    }
}

// ---------------------------------------------------------------------------
// Fused: sum 4 split-K partials -> log + linear bias -> trop_layernorm
// (median/IQR hybrid bitonic sort) -> relu -> exp.
// ---------------------------------------------------------------------------
__global__ __launch_bounds__(256) void ln_fuse_kernel(
    const float* __restrict__ P, const float* __restrict__ lb,
    const float* __restrict__ w, const float* __restrict__ b,
    float* __restrict__ Exout) {
    __shared__ float s[512];
    const int row = blockIdx.x;
    const int t = threadIdx.x;
    const size_t PS = (size_t)MROWS * 512;
    const float* P0 = P + row * 512;

    float s0 = P0[t]            + P0[PS + t]
             + P0[2 * PS + t]   + P0[3 * PS + t];
    float s1 = P0[t + 256]          + P0[PS + t + 256]
             + P0[2 * PS + t + 256] + P0[3 * PS + t + 256];
    const float h0 = logf(s0) + lb[t];
    const float h1 = logf(s1) + lb[t + 256];
    float v0 = h0, v1 = h1;

#pragma unroll
    for (int k = 2; k <= 512; k <<= 1) {
        if (k == 512) {
            float m = fminf(v0, v1), M = fmaxf(v0, v1);
            v0 = m; v1 = M;
        }
#pragma unroll
        for (int j = (k >> 1) > 128 ? 128 : (k >> 1); j >= 32; j >>= 1) {
            __syncthreads();
            s[t] = v0; s[t + 256] = v1;
            __syncthreads();
            float p0 = s[t ^ j];
            float p1 = s[(t ^ j) + 256];
            bool asc0 = ((t & k) == 0);
            bool asc1 = (((t + 256) & k) == 0);
            bool low = ((t & j) == 0);
            v0 = (low == asc0) ? fminf(v0, p0) : fmaxf(v0, p0);
            v1 = (low == asc1) ? fminf(v1, p1) : fmaxf(v1, p1);
        }
#pragma unroll
        for (int j = (k >> 1) > 16 ? 16 : (k >> 1); j >= 1; j >>= 1) {
            bool asc0 = ((t & k) == 0);
            bool asc1 = (((t + 256) & k) == 0);
            bool low = ((t & j) == 0);
            float p0 = __shfl_xor_sync(0xffffffffu, v0, j);
            float p1 = __shfl_xor_sync(0xffffffffu, v1, j);
            v0 = (low == asc0) ? fminf(v0, p0) : fmaxf(v0, p0);
            v1 = (low == asc1) ? fminf(v1, p1) : fmaxf(v1, p1);
        }
    }

    __syncthreads();
    if (t == 127) { s[0] = v0; s[3] = v1; }
    if (t == 128) { s[1] = v0; s[4] = v1; }
    if (t == 255) { s[2] = v0; }
    __syncthreads();
    const float q25 = s[0] + 0.75f * (s[1] - s[0]);
    const float med = s[2];
    const float q75 = s[3] + 0.25f * (s[4] - s[3]);
    const float inv = 1.0f / fmaxf(q75 - q25, 1e-6f);

    float o0 = fmaxf((h0 - med) * inv * w[t] + b[t], 0.0f);
    float o1 = fmaxf((h1 - med) * inv * w[t + 256] + b[t + 256], 0.0f);
    Exout[row * 512 + t]       = expf(o0);
    Exout[row * 512 + t + 256] = expf(o1);
}

// ---------------------------------------------------------------------------
// Final: sum 8 split-K partials of layer-3, log + bias -> d_out (1024x256)
// ---------------------------------------------------------------------------
__global__ __launch_bounds__(256) void final3_kernel(
    const float* __restrict__ P, const float* __restrict__ b3,
    float* __restrict__ out) {
    const int row = blockIdx.x;
    const int t = threadIdx.x;
    const size_t PS = (size_t)MROWS * 256;
    const float* P0 = P + row * 256 + t;
    float s = 0.0f;
#pragma unroll
    for (int kz = 0; kz < 8; kz++) s += P0[kz * PS];
    out[row * 256 + t] = logf(s) + b3[t];
}

// ---------------------------------------------------------------------------
extern "C" void kernel_launch(void* const* d_in, const int* in_sizes, int n_in,
                              void* d_out, int out_size) {
    const float* x    = (const float*)d_in[0];
    const float* w1   = (const float*)d_in[1];
    const float* b1   = (const float*)d_in[2];
    const float* ln1w = (const float*)d_in[3];
    const float* ln1b = (const float*)d_in[4];
    const float* w2   = (const float*)d_in[5];
    const float* b2   = (const float*)d_in[6];
    const float* ln2w = (const float*)d_in[7];
    const float* ln2b = (const float*)d_in[8];
    const float* w3   = (const float*)d_in[9];
    const float* b3   = (const float*)d_in[10];

    float *Ew1, *Ew2, *Ew3, *bufA, *bufB, *P;
    cudaGetSymbolAddress((void**)&Ew1, g_Ew1);
    cudaGetSymbolAddress((void**)&Ew2, g_Ew2);
    cudaGetSymbolAddress((void**)&Ew3, g_Ew3);
    cudaGetSymbolAddress((void**)&bufA, g_bufA);
    cudaGetSymbolAddress((void**)&bufB, g_bufB);
    cudaGetSymbolAddress((void**)&P, g_P);

    exp_all_kernel<<<1152, 256>>>(x, bufA, w1, Ew1, w2, Ew2, w3, Ew3);

    dim3 g12(512 / 128, 1024 / 128, 4);   // 4 x 8 x 4 = 128 CTAs
    dim3 g3(256 / 128, 1024 / 128, 8);    // 2 x 8 x 8 = 128 CTAs

    gemm_sk<128><<<g12, 256>>>(bufA, Ew1, P, 512);
    ln_fuse_kernel<<<1024, 256>>>(P, b1, ln1w, ln1b, bufB);
    gemm_sk<128><<<g12, 256>>>(bufB, Ew2, P, 512);
    ln_fuse_kernel<<<1024, 256>>>(P, b2, ln2w, ln2b, bufA);
    gemm_sk<64><<<g3, 256>>>(bufA, Ew3, P, 256);
    final3_kernel<<<1024, 256>>>(P, b3, (float*)d_out);
}

// round 9
// speedup vs baseline: 1.8394x; 1.8394x over previous
#include <cuda_runtime.h>
#include <cuda_bf16.h>
#include <math.h>
#include <cstdint>

// ---------------------------------------------------------------------------
// TropicalMLP: trop_linear(x;W,b) = log(exp(x) @ exp(W)^T) + b  (temp=1).
// exp values split fp32 = hi(bf16) + lo(bf16); GEMM = hh + hl + lh via
// legacy mma.sync.m16n8k16 bf16 (HMMA, compute_103-safe; tcgen05 is not
// available in this build: harness emits compute_103 PTX without 'a').
// Dropped lo*lo term: GEMM rel err ~1e-5 -> final ~2e-4 (gate 1e-3).
// ---------------------------------------------------------------------------

#define KDIM 512

__device__ float          g_H[1024 * 512];
__device__ __nv_bfloat16  g_Ah[1024 * 512];
__device__ __nv_bfloat16  g_Al[1024 * 512];
__device__ __nv_bfloat16  g_W1h[512 * 512];
__device__ __nv_bfloat16  g_W1l[512 * 512];
__device__ __nv_bfloat16  g_W2h[512 * 512];
__device__ __nv_bfloat16  g_W2l[512 * 512];
__device__ __nv_bfloat16  g_W3h[256 * 512];
__device__ __nv_bfloat16  g_W3l[256 * 512];

__device__ __forceinline__ uint32_t smem_to_u32(const void* p) {
    uint32_t a;
    asm("{ .reg .u64 t; cvta.to.shared.u64 t, %1; cvt.u32.u64 %0, t; }"
        : "=r"(a) : "l"(p));
    return a;
}

#define LDSM4(r0, r1, r2, r3, addr)                                        \
    asm volatile("ldmatrix.sync.aligned.m8n8.x4.shared.b16 {%0,%1,%2,%3}, [%4];" \
                 : "=r"(r0), "=r"(r1), "=r"(r2), "=r"(r3) : "r"(addr))

#define MMA16816(d, a, b)                                                  \
    asm volatile("mma.sync.aligned.m16n8k16.row.col.f32.bf16.bf16.f32 "    \
                 "{%0,%1,%2,%3}, {%4,%5,%6,%7}, {%8,%9}, {%0,%1,%2,%3};"   \
                 : "+f"((d)[0]), "+f"((d)[1]), "+f"((d)[2]), "+f"((d)[3])  \
                 : "r"((a)[0]), "r"((a)[1]), "r"((a)[2]), "r"((a)[3]),     \
                   "r"((b)[0]), "r"((b)[1]))

// ---------------------------------------------------------------------------
// exp + hi/lo split of x, w1, w2, w3 (float4 granular)
// ---------------------------------------------------------------------------
__global__ __launch_bounds__(256) void exp_split_kernel(
    const float* __restrict__ x,  __nv_bfloat16* __restrict__ xh, __nv_bfloat16* __restrict__ xl,
    const float* __restrict__ w1, __nv_bfloat16* __restrict__ w1h, __nv_bfloat16* __restrict__ w1l,
    const float* __restrict__ w2, __nv_bfloat16* __restrict__ w2h, __nv_bfloat16* __restrict__ w2l,
    const float* __restrict__ w3, __nv_bfloat16* __restrict__ w3h, __nv_bfloat16* __restrict__ w3l) {
    int i = blockIdx.x * 256 + threadIdx.x;  // float4 index
    const float* s; __nv_bfloat16 *dh, *dl; int off;
    if (i < 131072)      { s = x;  dh = xh;  dl = xl;  off = i; }
    else if (i < 196608) { s = w1; dh = w1h; dl = w1l; off = i - 131072; }
    else if (i < 262144) { s = w2; dh = w2h; dl = w2l; off = i - 196608; }
    else                 { s = w3; dh = w3h; dl = w3l; off = i - 262144; }
    float4 v = reinterpret_cast<const float4*>(s)[off];
    float e[4] = {expf(v.x), expf(v.y), expf(v.z), expf(v.w)};
#pragma unroll
    for (int j = 0; j < 4; j++) {
        __nv_bfloat16 hi = __float2bfloat16(e[j]);
        __nv_bfloat16 lo = __float2bfloat16(e[j] - __bfloat162float(hi));
        dh[off * 4 + j] = hi;
        dl[off * 4 + j] = lo;
    }
}

// ---------------------------------------------------------------------------
// HMMA GEMM:  C[m,n] = log( (Ah+Al)[m,:].(Bh+Bl)[n,:] ) + bias[n]
// 64x64 CTA tile, 4 warps (warp tile 32x32), K in 16 chunks of 32,
// double-buffered smem (padded 40-bf16 rows: conflict-free ldmatrix).
// Grid (OUT/64, 1024/64), 128 threads.
// ---------------------------------------------------------------------------
#define BKC 32          // K per chunk
#define LDS 40          // padded row stride in bf16 (80 B)

__global__ __launch_bounds__(128, 1) void gemm_mma(
    const __nv_bfloat16* __restrict__ Ah, const __nv_bfloat16* __restrict__ Al,
    const __nv_bfloat16* __restrict__ Bh, const __nv_bfloat16* __restrict__ Bl,
    const float* __restrict__ bias, float* __restrict__ C, int OUT) {
    // arrays: 0=Ah 1=Al 2=Bh 3=Bl
    __shared__ __nv_bfloat16 sm[2][4][64][LDS];

    const int tid  = threadIdx.x;
    const int lane = tid & 31;
    const int warp = tid >> 5;
    const int wm = (warp >> 1) * 32;
    const int wn = (warp & 1) * 32;
    const int bm = blockIdx.y * 64;
    const int bn = blockIdx.x * 64;

    const uint32_t sbase = smem_to_u32(sm);
    constexpr uint32_t BUFB = 4u * 64u * LDS * 2u;  // bytes per buffer
    constexpr uint32_t ARRB = 64u * LDS * 2u;       // bytes per array

    // ldmatrix lane addressing (byte offsets within a buffer)
    const int rowA = (lane & 15);
    const int chA  = lane >> 4;
    const int qB   = lane >> 3;
    const int rowB = ((qB >> 1) << 3) + (lane & 7);
    const int colB = (qB & 1) * 8;
    // A: arrays 0/1, tiles tm 0/1 ; B: arrays 2/3, pairs p 0/1
    uint32_t aAdr[2][2], bAdr[2][2];
#pragma unroll
    for (int arr = 0; arr < 2; arr++)
#pragma unroll
        for (int tm = 0; tm < 2; tm++)
            aAdr[arr][tm] = sbase + arr * ARRB +
                ((uint32_t)(wm + tm * 16 + rowA) * LDS + chA * 8) * 2;
#pragma unroll
    for (int arr = 0; arr < 2; arr++)
#pragma unroll
        for (int p = 0; p < 2; p++)
            bAdr[arr][p] = sbase + (2 + arr) * ARRB +
                ((uint32_t)(wn + p * 16 + rowB) * LDS + colB) * 2;

    // global prefetch mapping: 2 (row,seg) slots per thread per array
    int grow[2], gseg[2];
#pragma unroll
    for (int i = 0; i < 2; i++) {
        int lin = tid * 2 + i;
        grow[i] = lin >> 2;
        gseg[i] = lin & 3;
    }
    const __nv_bfloat16* gp[4];
    gp[0] = Ah + (size_t)bm * KDIM;
    gp[1] = Al + (size_t)bm * KDIM;
    gp[2] = Bh + (size_t)bn * KDIM;
    gp[3] = Bl + (size_t)bn * KDIM;

    float acc[2][4][4] = {};
    uint4 pf[4][2];

    // prologue: chunk 0 -> buf 0
#pragma unroll
    for (int a = 0; a < 4; a++)
#pragma unroll
        for (int i = 0; i < 2; i++)
            pf[a][i] = *reinterpret_cast<const uint4*>(
                gp[a] + (size_t)grow[i] * KDIM + gseg[i] * 8);
#pragma unroll
    for (int a = 0; a < 4; a++)
#pragma unroll
        for (int i = 0; i < 2; i++)
            *reinterpret_cast<uint4*>(&sm[0][a][grow[i]][gseg[i] * 8]) = pf[a][i];
    __syncthreads();

#pragma unroll 1
    for (int c = 0; c < 16; c++) {
        const int buf = c & 1;
        const bool more = (c + 1 < 16);
        if (more) {
            const int k0 = (c + 1) * BKC;
#pragma unroll
            for (int a = 0; a < 4; a++)
#pragma unroll
                for (int i = 0; i < 2; i++)
                    pf[a][i] = *reinterpret_cast<const uint4*>(
                        gp[a] + (size_t)grow[i] * KDIM + k0 + gseg[i] * 8);
        }

        const uint32_t bo = buf * BUFB;
#pragma unroll
        for (int s = 0; s < 2; s++) {
            const uint32_t so = s * 32;  // 16 bf16 = 32 B
            uint32_t ah[2][4], al[2][4], bh[2][4], bl[2][4];
#pragma unroll
            for (int tm = 0; tm < 2; tm++) {
                LDSM4(ah[tm][0], ah[tm][1], ah[tm][2], ah[tm][3], aAdr[0][tm] + bo + so);
                LDSM4(al[tm][0], al[tm][1], al[tm][2], al[tm][3], aAdr[1][tm] + bo + so);
            }
#pragma unroll
            for (int p = 0; p < 2; p++) {
                LDSM4(bh[p][0], bh[p][1], bh[p][2], bh[p][3], bAdr[0][p] + bo + so);
                LDSM4(bl[p][0], bl[p][1], bl[p][2], bl[p][3], bAdr[1][p] + bo + so);
            }
#pragma unroll
            for (int tm = 0; tm < 2; tm++)
#pragma unroll
                for (int tn = 0; tn < 4; tn++) {
                    uint32_t* bhp = &bh[tn >> 1][(tn & 1) * 2];
                    uint32_t* blp = &bl[tn >> 1][(tn & 1) * 2];
                    MMA16816(acc[tm][tn], ah[tm], bhp);   // hi*hi
                    MMA16816(acc[tm][tn], ah[tm], blp);   // hi*lo
                    MMA16816(acc[tm][tn], al[tm], bhp);   // lo*hi
                }
        }

        if (more) {
            const int nb = buf ^ 1;
#pragma unroll
            for (int a = 0; a < 4; a++)
#pragma unroll
                for (int i = 0; i < 2; i++)
                    *reinterpret_cast<uint4*>(&sm[nb][a][grow[i]][gseg[i] * 8]) = pf[a][i];
            __syncthreads();
        }
    }

    // epilogue: log + bias.  mma D layout: d0,d1 -> (row lane>>2, col (lane&3)*2, +1),
    // d2,d3 -> row+8.
    const int er = lane >> 2;
    const int ec = (lane & 3) * 2;
#pragma unroll
    for (int tm = 0; tm < 2; tm++)
#pragma unroll
        for (int tn = 0; tn < 4; tn++) {
            const int row = bm + wm + tm * 16 + er;
            const int col = bn + wn + tn * 8 + ec;
            float2 o0, o1;
            o0.x = logf(acc[tm][tn][0]) + bias[col];
            o0.y = logf(acc[tm][tn][1]) + bias[col + 1];
            o1.x = logf(acc[tm][tn][2]) + bias[col];
            o1.y = logf(acc[tm][tn][3]) + bias[col + 1];
            *reinterpret_cast<float2*>(C + (size_t)row * OUT + col) = o0;
            *reinterpret_cast<float2*>(C + (size_t)(row + 8) * OUT + col) = o1;
        }
}

// ---------------------------------------------------------------------------
// trop_layernorm (median/IQR hybrid bitonic) + relu + exp + bf16 hi/lo split.
// ---------------------------------------------------------------------------
__global__ __launch_bounds__(256) void ln_kernel(
    const float* __restrict__ H, const float* __restrict__ w,
    const float* __restrict__ b,
    __nv_bfloat16* __restrict__ Oh, __nv_bfloat16* __restrict__ Ol) {
    __shared__ float s[512];
    const int row = blockIdx.x;
    const int t = threadIdx.x;
    const float* Hrow = H + row * 512;

    const float h0 = Hrow[t];
    const float h1 = Hrow[t + 256];
    float v0 = h0, v1 = h1;

#pragma unroll
    for (int k = 2; k <= 512; k <<= 1) {
        if (k == 512) {
            float m = fminf(v0, v1), M = fmaxf(v0, v1);
            v0 = m; v1 = M;
        }
#pragma unroll
        for (int j = (k >> 1) > 128 ? 128 : (k >> 1); j >= 32; j >>= 1) {
            __syncthreads();
            s[t] = v0; s[t + 256] = v1;
            __syncthreads();
            float p0 = s[t ^ j];
            float p1 = s[(t ^ j) + 256];
            bool asc0 = ((t & k) == 0);
            bool asc1 = (((t + 256) & k) == 0);
            bool low = ((t & j) == 0);
            v0 = (low == asc0) ? fminf(v0, p0) : fmaxf(v0, p0);
            v1 = (low == asc1) ? fminf(v1, p1) : fmaxf(v1, p1);
        }
#pragma unroll
        for (int j = (k >> 1) > 16 ? 16 : (k >> 1); j >= 1; j >>= 1) {
            bool asc0 = ((t & k) == 0);
            bool asc1 = (((t + 256) & k) == 0);
            bool low = ((t & j) == 0);
            float p0 = __shfl_xor_sync(0xffffffffu, v0, j);
            float p1 = __shfl_xor_sync(0xffffffffu, v1, j);
            v0 = (low == asc0) ? fminf(v0, p0) : fmaxf(v0, p0);
            v1 = (low == asc1) ? fminf(v1, p1) : fmaxf(v1, p1);
        }
    }

    __syncthreads();
    if (t == 127) { s[0] = v0; s[3] = v1; }
    if (t == 128) { s[1] = v0; s[4] = v1; }
    if (t == 255) { s[2] = v0; }
    __syncthreads();
    const float q25 = s[0] + 0.75f * (s[1] - s[0]);
    const float med = s[2];
    const float q75 = s[3] + 0.25f * (s[4] - s[3]);
    const float inv = 1.0f / fmaxf(q75 - q25, 1e-6f);

#pragma unroll
    for (int half = 0; half < 2; half++) {
        const int idx = t + half * 256;
        const float h = half ? h1 : h0;
        float o = fmaxf((h - med) * inv * w[idx] + b[idx], 0.0f);
        float e = expf(o);
        __nv_bfloat16 hi = __float2bfloat16(e);
        __nv_bfloat16 lo = __float2bfloat16(e - __bfloat162float(hi));
        Oh[row * 512 + idx] = hi;
        Ol[row * 512 + idx] = lo;
    }
}

// ---------------------------------------------------------------------------
extern "C" void kernel_launch(void* const* d_in, const int* in_sizes, int n_in,
                              void* d_out, int out_size) {
    const float* x    = (const float*)d_in[0];
    const float* w1   = (const float*)d_in[1];
    const float* b1   = (const float*)d_in[2];
    const float* ln1w = (const float*)d_in[3];
    const float* ln1b = (const float*)d_in[4];
    const float* w2   = (const float*)d_in[5];
    const float* b2   = (const float*)d_in[6];
    const float* ln2w = (const float*)d_in[7];
    const float* ln2b = (const float*)d_in[8];
    const float* w3   = (const float*)d_in[9];
    const float* b3   = (const float*)d_in[10];

    float* H;
    __nv_bfloat16 *Ah, *Al, *W1h, *W1l, *W2h, *W2l, *W3h, *W3l;
    cudaGetSymbolAddress((void**)&H, g_H);
    cudaGetSymbolAddress((void**)&Ah, g_Ah);
    cudaGetSymbolAddress((void**)&Al, g_Al);
    cudaGetSymbolAddress((void**)&W1h, g_W1h);
    cudaGetSymbolAddress((void**)&W1l, g_W1l);
    cudaGetSymbolAddress((void**)&W2h, g_W2h);
    cudaGetSymbolAddress((void**)&W2l, g_W2l);
    cudaGetSymbolAddress((void**)&W3h, g_W3h);
    cudaGetSymbolAddress((void**)&W3l, g_W3l);

    exp_split_kernel<<<1152, 256>>>(x, Ah, Al, w1, W1h, W1l, w2, W2h, W2l,
                                    w3, W3h, W3l);

    dim3 g12(512 / 64, 1024 / 64);   // 8 x 16 = 128 CTAs
    dim3 g3(256 / 64, 1024 / 64);    // 4 x 16 = 64 CTAs

    gemm_mma<<<g12, 128>>>(Ah, Al, W1h, W1l, b1, H, 512);
    ln_kernel<<<1024, 256>>>(H, ln1w, ln1b, Ah, Al);
    gemm_mma<<<g12, 128>>>(Ah, Al, W2h, W2l, b2, H, 512);
    ln_kernel<<<1024, 256>>>(H, ln2w, ln2b, Ah, Al);
    gemm_mma<<<g3, 128>>>(Ah, Al, W3h, W3l, b3, (float*)d_out, 256);
}

// round 10
// speedup vs baseline: 2.0322x; 1.1048x over previous
#include <cuda_runtime.h>
#include <cuda_bf16.h>
#include <math.h>
#include <cstdint>

// ---------------------------------------------------------------------------
// TropicalMLP: trop_linear(x;W,b) = log(exp(x) @ exp(W)^T) + b  (temp=1).
// exp values split fp32 = hi(bf16) + lo(bf16); GEMM = hh + hl + lh via
// legacy mma.sync.m16n8k16 bf16 (compute_103-safe; tcgen05 unavailable).
// R9: 256-thread GEMM CTAs (8 warps, warp tile 16x32) -> 2 warps/SMSP to
// hide ldmatrix/mma latency.  Dropped lo*lo: final rel err ~1.2e-5.
// ---------------------------------------------------------------------------

#define KDIM 512

__device__ float          g_H[1024 * 512];
__device__ __nv_bfloat16  g_Ah[1024 * 512];
__device__ __nv_bfloat16  g_Al[1024 * 512];
__device__ __nv_bfloat16  g_W1h[512 * 512];
__device__ __nv_bfloat16  g_W1l[512 * 512];
__device__ __nv_bfloat16  g_W2h[512 * 512];
__device__ __nv_bfloat16  g_W2l[512 * 512];
__device__ __nv_bfloat16  g_W3h[256 * 512];
__device__ __nv_bfloat16  g_W3l[256 * 512];

__device__ __forceinline__ uint32_t smem_to_u32(const void* p) {
    uint32_t a;
    asm("{ .reg .u64 t; cvta.to.shared.u64 t, %1; cvt.u32.u64 %0, t; }"
        : "=r"(a) : "l"(p));
    return a;
}

#define LDSM4(r0, r1, r2, r3, addr)                                        \
    asm volatile("ldmatrix.sync.aligned.m8n8.x4.shared.b16 {%0,%1,%2,%3}, [%4];" \
                 : "=r"(r0), "=r"(r1), "=r"(r2), "=r"(r3) : "r"(addr))

#define MMA16816(d, a, b)                                                  \
    asm volatile("mma.sync.aligned.m16n8k16.row.col.f32.bf16.bf16.f32 "    \
                 "{%0,%1,%2,%3}, {%4,%5,%6,%7}, {%8,%9}, {%0,%1,%2,%3};"   \
                 : "+f"((d)[0]), "+f"((d)[1]), "+f"((d)[2]), "+f"((d)[3])  \
                 : "r"((a)[0]), "r"((a)[1]), "r"((a)[2]), "r"((a)[3]),     \
                   "r"((b)[0]), "r"((b)[1]))

// ---------------------------------------------------------------------------
// exp + hi/lo split of x, w1, w2, w3 (float4 granular)
// ---------------------------------------------------------------------------
__global__ __launch_bounds__(256) void exp_split_kernel(
    const float* __restrict__ x,  __nv_bfloat16* __restrict__ xh, __nv_bfloat16* __restrict__ xl,
    const float* __restrict__ w1, __nv_bfloat16* __restrict__ w1h, __nv_bfloat16* __restrict__ w1l,
    const float* __restrict__ w2, __nv_bfloat16* __restrict__ w2h, __nv_bfloat16* __restrict__ w2l,
    const float* __restrict__ w3, __nv_bfloat16* __restrict__ w3h, __nv_bfloat16* __restrict__ w3l) {
    int i = blockIdx.x * 256 + threadIdx.x;  // float4 index
    const float* s; __nv_bfloat16 *dh, *dl; int off;
    if (i < 131072)      { s = x;  dh = xh;  dl = xl;  off = i; }
    else if (i < 196608) { s = w1; dh = w1h; dl = w1l; off = i - 131072; }
    else if (i < 262144) { s = w2; dh = w2h; dl = w2l; off = i - 196608; }
    else                 { s = w3; dh = w3h; dl = w3l; off = i - 262144; }
    float4 v = reinterpret_cast<const float4*>(s)[off];
    float e[4] = {expf(v.x), expf(v.y), expf(v.z), expf(v.w)};
#pragma unroll
    for (int j = 0; j < 4; j++) {
        __nv_bfloat16 hi = __float2bfloat16(e[j]);
        __nv_bfloat16 lo = __float2bfloat16(e[j] - __bfloat162float(hi));
        dh[off * 4 + j] = hi;
        dl[off * 4 + j] = lo;
    }
}

// ---------------------------------------------------------------------------
// HMMA GEMM:  C[m,n] = log( (Ah+Al)[m,:].(Bh+Bl)[n,:] ) + bias[n]
// 64x64 CTA tile, 8 warps (warp tile 16x32), K in 16 chunks of 32,
// double-buffered smem (padded 40-bf16 rows), register prefetch.
// Grid (OUT/64, 1024/64), 256 threads.
// ---------------------------------------------------------------------------
#define BKC 32          // K per chunk
#define LDS 40          // padded row stride in bf16 (80 B)

__global__ __launch_bounds__(256, 1) void gemm_mma(
    const __nv_bfloat16* __restrict__ Ah, const __nv_bfloat16* __restrict__ Al,
    const __nv_bfloat16* __restrict__ Bh, const __nv_bfloat16* __restrict__ Bl,
    const float* __restrict__ bias, float* __restrict__ C, int OUT) {
    // arrays: 0=Ah 1=Al 2=Bh 3=Bl
    __shared__ __nv_bfloat16 sm[2][4][64][LDS];

    const int tid  = threadIdx.x;
    const int lane = tid & 31;
    const int warp = tid >> 5;
    const int wm = (warp >> 1) * 16;   // 4 m-groups of 16
    const int wn = (warp & 1) * 32;    // 2 n-groups of 32
    const int bm = blockIdx.y * 64;
    const int bn = blockIdx.x * 64;

    const uint32_t sbase = smem_to_u32(sm);
    constexpr uint32_t BUFB = 4u * 64u * LDS * 2u;  // bytes per buffer
    constexpr uint32_t ARRB = 64u * LDS * 2u;       // bytes per array

    // ldmatrix lane addressing (byte offsets within a buffer)
    const int rowA = (lane & 15);
    const int chA  = lane >> 4;
    const int qB   = lane >> 3;
    const int rowB = ((qB >> 1) << 3) + (lane & 7);
    const int colB = (qB & 1) * 8;
    uint32_t aAdr[2];                 // arr 0/1 (hi/lo), single 16-row m tile
#pragma unroll
    for (int arr = 0; arr < 2; arr++)
        aAdr[arr] = sbase + arr * ARRB +
            ((uint32_t)(wm + rowA) * LDS + chA * 8) * 2;
    uint32_t bAdr[2][2];              // arr(hi/lo) x p(16-row n group)
#pragma unroll
    for (int arr = 0; arr < 2; arr++)
#pragma unroll
        for (int p = 0; p < 2; p++)
            bAdr[arr][p] = sbase + (2 + arr) * ARRB +
                ((uint32_t)(wn + p * 16 + rowB) * LDS + colB) * 2;

    // global prefetch mapping: 1 uint4 per thread per array
    const int grow = tid >> 2;        // 0..63
    const int gseg = tid & 3;         // 4 segs of 8 bf16
    const __nv_bfloat16* gp[4];
    gp[0] = Ah + (size_t)bm * KDIM;
    gp[1] = Al + (size_t)bm * KDIM;
    gp[2] = Bh + (size_t)bn * KDIM;
    gp[3] = Bl + (size_t)bn * KDIM;

    float acc[4][4] = {};
    uint4 pf[4];

    // prologue: chunk 0 -> buf 0
#pragma unroll
    for (int a = 0; a < 4; a++)
        pf[a] = *reinterpret_cast<const uint4*>(
            gp[a] + (size_t)grow * KDIM + gseg * 8);
#pragma unroll
    for (int a = 0; a < 4; a++)
        *reinterpret_cast<uint4*>(&sm[0][a][grow][gseg * 8]) = pf[a];
    __syncthreads();

#pragma unroll 1
    for (int c = 0; c < 16; c++) {
        const int buf = c & 1;
        const bool more = (c + 1 < 16);
        if (more) {
            const int k0 = (c + 1) * BKC;
#pragma unroll
            for (int a = 0; a < 4; a++)
                pf[a] = *reinterpret_cast<const uint4*>(
                    gp[a] + (size_t)grow * KDIM + k0 + gseg * 8);
        }

        const uint32_t bo = buf * BUFB;
#pragma unroll
        for (int s = 0; s < 2; s++) {
            const uint32_t so = s * 32;  // 16 bf16 = 32 B
            uint32_t ah[4], al[4], bh[2][4], bl[2][4];
            LDSM4(ah[0], ah[1], ah[2], ah[3], aAdr[0] + bo + so);
            LDSM4(al[0], al[1], al[2], al[3], aAdr[1] + bo + so);
#pragma unroll
            for (int p = 0; p < 2; p++) {
                LDSM4(bh[p][0], bh[p][1], bh[p][2], bh[p][3], bAdr[0][p] + bo + so);
                LDSM4(bl[p][0], bl[p][1], bl[p][2], bl[p][3], bAdr[1][p] + bo + so);
            }
#pragma unroll
            for (int tn = 0; tn < 4; tn++) {
                uint32_t* bhp = &bh[tn >> 1][(tn & 1) * 2];
                uint32_t* blp = &bl[tn >> 1][(tn & 1) * 2];
                MMA16816(acc[tn], ah, bhp);   // hi*hi
                MMA16816(acc[tn], ah, blp);   // hi*lo
                MMA16816(acc[tn], al, bhp);   // lo*hi
            }
        }

        if (more) {
            const int nb = buf ^ 1;
#pragma unroll
            for (int a = 0; a < 4; a++)
                *reinterpret_cast<uint4*>(&sm[nb][a][grow][gseg * 8]) = pf[a];
            __syncthreads();
        }
    }

    // epilogue: log + bias.  mma D layout: d0,d1 -> (lane>>2, (lane&3)*2 +0/1),
    // d2,d3 -> row+8.
    const int er = lane >> 2;
    const int ec = (lane & 3) * 2;
#pragma unroll
    for (int tn = 0; tn < 4; tn++) {
        const int row = bm + wm + er;
        const int col = bn + wn + tn * 8 + ec;
        float2 o0, o1;
        o0.x = logf(acc[tn][0]) + bias[col];
        o0.y = logf(acc[tn][1]) + bias[col + 1];
        o1.x = logf(acc[tn][2]) + bias[col];
        o1.y = logf(acc[tn][3]) + bias[col + 1];
        *reinterpret_cast<float2*>(C + (size_t)row * OUT + col) = o0;
        *reinterpret_cast<float2*>(C + (size_t)(row + 8) * OUT + col) = o1;
    }
}

// ---------------------------------------------------------------------------
// trop_layernorm (median/IQR hybrid bitonic) + relu + exp + bf16 hi/lo split.
// ---------------------------------------------------------------------------
__global__ __launch_bounds__(256) void ln_kernel(
    const float* __restrict__ H, const float* __restrict__ w,
    const float* __restrict__ b,
    __nv_bfloat16* __restrict__ Oh, __nv_bfloat16* __restrict__ Ol) {
    __shared__ float s[512];
    const int row = blockIdx.x;
    const int t = threadIdx.x;
    const float* Hrow = H + row * 512;

    const float h0 = Hrow[t];
    const float h1 = Hrow[t + 256];
    float v0 = h0, v1 = h1;

#pragma unroll
    for (int k = 2; k <= 512; k <<= 1) {
        if (k == 512) {
            float m = fminf(v0, v1), M = fmaxf(v0, v1);
            v0 = m; v1 = M;
        }
#pragma unroll
        for (int j = (k >> 1) > 128 ? 128 : (k >> 1); j >= 32; j >>= 1) {
            __syncthreads();
            s[t] = v0; s[t + 256] = v1;
            __syncthreads();
            float p0 = s[t ^ j];
            float p1 = s[(t ^ j) + 256];
            bool asc0 = ((t & k) == 0);
            bool asc1 = (((t + 256) & k) == 0);
            bool low = ((t & j) == 0);
            v0 = (low == asc0) ? fminf(v0, p0) : fmaxf(v0, p0);
            v1 = (low == asc1) ? fminf(v1, p1) : fmaxf(v1, p1);
        }
#pragma unroll
        for (int j = (k >> 1) > 16 ? 16 : (k >> 1); j >= 1; j >>= 1) {
            bool asc0 = ((t & k) == 0);
            bool asc1 = (((t + 256) & k) == 0);
            bool low = ((t & j) == 0);
            float p0 = __shfl_xor_sync(0xffffffffu, v0, j);
            float p1 = __shfl_xor_sync(0xffffffffu, v1, j);
            v0 = (low == asc0) ? fminf(v0, p0) : fmaxf(v0, p0);
            v1 = (low == asc1) ? fminf(v1, p1) : fmaxf(v1, p1);
        }
    }

    __syncthreads();
    if (t == 127) { s[0] = v0; s[3] = v1; }
    if (t == 128) { s[1] = v0; s[4] = v1; }
    if (t == 255) { s[2] = v0; }
    __syncthreads();
    const float q25 = s[0] + 0.75f * (s[1] - s[0]);
    const float med = s[2];
    const float q75 = s[3] + 0.25f * (s[4] - s[3]);
    const float inv = 1.0f / fmaxf(q75 - q25, 1e-6f);

#pragma unroll
    for (int half = 0; half < 2; half++) {
        const int idx = t + half * 256;
        const float h = half ? h1 : h0;
        float o = fmaxf((h - med) * inv * w[idx] + b[idx], 0.0f);
        float e = expf(o);
        __nv_bfloat16 hi = __float2bfloat16(e);
        __nv_bfloat16 lo = __float2bfloat16(e - __bfloat162float(hi));
        Oh[row * 512 + idx] = hi;
        Ol[row * 512 + idx] = lo;
    }
}

// ---------------------------------------------------------------------------
extern "C" void kernel_launch(void* const* d_in, const int* in_sizes, int n_in,
                              void* d_out, int out_size) {
    const float* x    = (const float*)d_in[0];
    const float* w1   = (const float*)d_in[1];
    const float* b1   = (const float*)d_in[2];
    const float* ln1w = (const float*)d_in[3];
    const float* ln1b = (const float*)d_in[4];
    const float* w2   = (const float*)d_in[5];
    const float* b2   = (const float*)d_in[6];
    const float* ln2w = (const float*)d_in[7];
    const float* ln2b = (const float*)d_in[8];
    const float* w3   = (const float*)d_in[9];
    const float* b3   = (const float*)d_in[10];

    float* H;
    __nv_bfloat16 *Ah, *Al, *W1h, *W1l, *W2h, *W2l, *W3h, *W3l;
    cudaGetSymbolAddress((void**)&H, g_H);
    cudaGetSymbolAddress((void**)&Ah, g_Ah);
    cudaGetSymbolAddress((void**)&Al, g_Al);
    cudaGetSymbolAddress((void**)&W1h, g_W1h);
    cudaGetSymbolAddress((void**)&W1l, g_W1l);
    cudaGetSymbolAddress((void**)&W2h, g_W2h);
    cudaGetSymbolAddress((void**)&W2l, g_W2l);
    cudaGetSymbolAddress((void**)&W3h, g_W3h);
    cudaGetSymbolAddress((void**)&W3l, g_W3l);

    exp_split_kernel<<<1152, 256>>>(x, Ah, Al, w1, W1h, W1l, w2, W2h, W2l,
                                    w3, W3h, W3l);

    dim3 g12(512 / 64, 1024 / 64);   // 8 x 16 = 128 CTAs
    dim3 g3(256 / 64, 1024 / 64);    // 4 x 16 = 64 CTAs

    gemm_mma<<<g12, 256>>>(Ah, Al, W1h, W1l, b1, H, 512);
    ln_kernel<<<1024, 256>>>(H, ln1w, ln1b, Ah, Al);
    gemm_mma<<<g12, 256>>>(Ah, Al, W2h, W2l, b2, H, 512);
    ln_kernel<<<1024, 256>>>(H, ln2w, ln2b, Ah, Al);
    gemm_mma<<<g3, 256>>>(Ah, Al, W3h, W3l, b3, (float*)d_out, 256);
}

// round 12
// speedup vs baseline: 2.1386x; 1.0524x over previous
#include <cuda_runtime.h>
#include <cuda_bf16.h>
#include <math.h>
#include <cstdint>

// ---------------------------------------------------------------------------
// TropicalMLP: trop_linear(x;W,b) = log(exp(x) @ exp(W)^T) + b  (temp=1).
// exp values split fp32 = hi(bf16) + lo(bf16); GEMM = hh + hl + lh via
// mma.sync.m16n8k16 bf16.  R10: cp.async 3-stage pipeline + whole-chunk
// fragment preload (hide LDSM latency) + 32x64 layer-3 tiles (128 CTAs).
// ---------------------------------------------------------------------------

#define KDIM 512
#define BKC  32          // K per chunk
#define LDSP 40          // padded row stride in bf16 (80 B)

__device__ float          g_H[1024 * 512];
__device__ __nv_bfloat16  g_Ah[1024 * 512];
__device__ __nv_bfloat16  g_Al[1024 * 512];
__device__ __nv_bfloat16  g_W1h[512 * 512];
__device__ __nv_bfloat16  g_W1l[512 * 512];
__device__ __nv_bfloat16  g_W2h[512 * 512];
__device__ __nv_bfloat16  g_W2l[512 * 512];
__device__ __nv_bfloat16  g_W3h[256 * 512];
__device__ __nv_bfloat16  g_W3l[256 * 512];

__device__ __forceinline__ uint32_t smem_to_u32(const void* p) {
    uint32_t a;
    asm("{ .reg .u64 t; cvta.to.shared.u64 t, %1; cvt.u32.u64 %0, t; }"
        : "=r"(a) : "l"(p));
    return a;
}

#define LDSM4(r0, r1, r2, r3, addr)                                        \
    asm volatile("ldmatrix.sync.aligned.m8n8.x4.shared.b16 {%0,%1,%2,%3}, [%4];" \
                 : "=r"(r0), "=r"(r1), "=r"(r2), "=r"(r3) : "r"(addr))

#define MMA16816(d, a, b)                                                  \
    asm volatile("mma.sync.aligned.m16n8k16.row.col.f32.bf16.bf16.f32 "    \
                 "{%0,%1,%2,%3}, {%4,%5,%6,%7}, {%8,%9}, {%0,%1,%2,%3};"   \
                 : "+f"((d)[0]), "+f"((d)[1]), "+f"((d)[2]), "+f"((d)[3])  \
                 : "r"((a)[0]), "r"((a)[1]), "r"((a)[2]), "r"((a)[3]),     \
                   "r"((b)[0]), "r"((b)[1]))

#define CP_ASYNC16(dst, src)                                               \
    asm volatile("cp.async.ca.shared.global [%0], [%1], 16;"               \
                 :: "r"(dst), "l"(src))
#define CP_COMMIT() asm volatile("cp.async.commit_group;" ::: "memory")
#define CP_WAIT1()  asm volatile("cp.async.wait_group 1;" ::: "memory")

// ---------------------------------------------------------------------------
// exp + hi/lo split of x, w1, w2, w3 (float4 granular)
// ---------------------------------------------------------------------------
__global__ __launch_bounds__(256) void exp_split_kernel(
    const float* __restrict__ x,  __nv_bfloat16* __restrict__ xh, __nv_bfloat16* __restrict__ xl,
    const float* __restrict__ w1, __nv_bfloat16* __restrict__ w1h, __nv_bfloat16* __restrict__ w1l,
    const float* __restrict__ w2, __nv_bfloat16* __restrict__ w2h, __nv_bfloat16* __restrict__ w2l,
    const float* __restrict__ w3, __nv_bfloat16* __restrict__ w3h, __nv_bfloat16* __restrict__ w3l) {
    int i = blockIdx.x * 256 + threadIdx.x;  // float4 index
    const float* s; __nv_bfloat16 *dh, *dl; int off;
    if (i < 131072)      { s = x;  dh = xh;  dl = xl;  off = i; }
    else if (i < 196608) { s = w1; dh = w1h; dl = w1l; off = i - 131072; }
    else if (i < 262144) { s = w2; dh = w2h; dl = w2l; off = i - 196608; }
    else                 { s = w3; dh = w3h; dl = w3l; off = i - 262144; }
    float4 v = reinterpret_cast<const float4*>(s)[off];
    float e[4] = {expf(v.x), expf(v.y), expf(v.z), expf(v.w)};
#pragma unroll
    for (int j = 0; j < 4; j++) {
        __nv_bfloat16 hi = __float2bfloat16(e[j]);
        __nv_bfloat16 lo = __float2bfloat16(e[j] - __bfloat162float(hi));
        dh[off * 4 + j] = hi;
        dl[off * 4 + j] = lo;
    }
}

// ---------------------------------------------------------------------------
// HMMA GEMM:  C[m,n] = log( (Ah+Al)[m,:].(Bh+Bl)[n,:] ) + bias[n]
// BM x 64 CTA tile, 8 warps, warp tile 16 x WN.  K in 16 chunks of 32,
// 3-stage cp.async pipeline, whole-chunk fragment preload.
// Grid (OUT/64, 1024/BM), 256 threads.
// ---------------------------------------------------------------------------
template <int BM, int WN>
__global__ __launch_bounds__(256, 1) void gemm_mma(
    const __nv_bfloat16* __restrict__ Ah, const __nv_bfloat16* __restrict__ Al,
    const __nv_bfloat16* __restrict__ Bh, const __nv_bfloat16* __restrict__ Bl,
    const float* __restrict__ bias, float* __restrict__ C, int OUT) {
    constexpr int BN = 64, S = 3;
    constexpr int PN  = WN / 16;     // B 16-row groups per warp (1 or 2)
    constexpr int TNC = WN / 8;      // mma n-tiles per warp (2 or 4)
    constexpr int NWN = BN / WN;     // warps along N

    __shared__ __align__(16) __nv_bfloat16 sA[S][2][BM][LDSP];
    __shared__ __align__(16) __nv_bfloat16 sB[S][2][BN][LDSP];

    const int tid  = threadIdx.x;
    const int lane = tid & 31;
    const int warp = tid >> 5;
    const int wm = (warp / NWN) * 16;
    const int wn = (warp % NWN) * WN;
    const int bm = blockIdx.y * BM;
    const int bn = blockIdx.x * BN;

    const uint32_t sAb = smem_to_u32(sA);
    const uint32_t sBb = smem_to_u32(sB);
    constexpr uint32_t A_ARR = BM * LDSP * 2, A_STG = 2 * A_ARR;
    constexpr uint32_t B_ARR = BN * LDSP * 2, B_STG = 2 * B_ARR;

    // cp.async mapping: thread -> (row, 16B seg)
    const int grow = tid >> 2, gseg = tid & 3;
    const __nv_bfloat16* gpA[2] = {Ah + (size_t)bm * KDIM, Al + (size_t)bm * KDIM};
    const __nv_bfloat16* gpB[2] = {Bh + (size_t)bn * KDIM, Bl + (size_t)bn * KDIM};

    // ldmatrix lane addressing
    const int rowA = lane & 15, chA = lane >> 4;
    const int qB = lane >> 3;
    const int rowB = ((qB >> 1) << 3) + (lane & 7), colB = (qB & 1) * 8;
    uint32_t aBase[2], bBase[2][PN];
#pragma unroll
    for (int a = 0; a < 2; a++)
        aBase[a] = sAb + a * A_ARR + ((uint32_t)(wm + rowA) * LDSP + chA * 8) * 2;
#pragma unroll
    for (int a = 0; a < 2; a++)
#pragma unroll
        for (int p = 0; p < PN; p++)
            bBase[a][p] = sBb + a * B_ARR +
                ((uint32_t)(wn + p * 16 + rowB) * LDSP + colB) * 2;

    float acc[TNC][4] = {};

    auto copy_chunk = [&](int c, int buf) {
        const int k0 = c * BKC;
        if (tid < BM * 4) {
#pragma unroll
            for (int a = 0; a < 2; a++) {
                uint32_t dst = sAb + buf * A_STG + a * A_ARR +
                               ((uint32_t)grow * LDSP + gseg * 8) * 2;
                CP_ASYNC16(dst, gpA[a] + (size_t)grow * KDIM + k0 + gseg * 8);
            }
        }
#pragma unroll
        for (int a = 0; a < 2; a++) {
            uint32_t dst = sBb + buf * B_STG + a * B_ARR +
                           ((uint32_t)grow * LDSP + gseg * 8) * 2;
            CP_ASYNC16(dst, gpB[a] + (size_t)grow * KDIM + k0 + gseg * 8);
        }
        CP_COMMIT();
    };

    copy_chunk(0, 0);
    copy_chunk(1, 1);

#pragma unroll 1
    for (int c = 0; c < 16; c++) {
        CP_WAIT1();              // this thread's chunk-c copies landed
        __syncthreads();         // visible to all; all done computing c-1
        if (c + 2 < 16) copy_chunk(c + 2, (c + 2) % S);
        else            CP_COMMIT();   // keep group numbering uniform

        const uint32_t ao = (c % S) * A_STG, bo = (c % S) * B_STG;
        // preload ALL fragments for both 16-K steps of this chunk
        uint32_t ah[2][4], al[2][4], bh[2][PN][4], bl[2][PN][4];
#pragma unroll
        for (int s = 0; s < 2; s++) {
            const uint32_t so = s * 32;
            LDSM4(ah[s][0], ah[s][1], ah[s][2], ah[s][3], aBase[0] + ao + so);
            LDSM4(al[s][0], al[s][1], al[s][2], al[s][3], aBase[1] + ao + so);
#pragma unroll
            for (int p = 0; p < PN; p++) {
                LDSM4(bh[s][p][0], bh[s][p][1], bh[s][p][2], bh[s][p][3],
                      bBase[0][p] + bo + so);
                LDSM4(bl[s][p][0], bl[s][p][1], bl[s][p][2], bl[s][p][3],
                      bBase[1][p] + bo + so);
            }
        }
#pragma unroll
        for (int s = 0; s < 2; s++)
#pragma unroll
            for (int tn = 0; tn < TNC; tn++) {
                uint32_t* bhp = &bh[s][tn >> 1][(tn & 1) * 2];
                uint32_t* blp = &bl[s][tn >> 1][(tn & 1) * 2];
                MMA16816(acc[tn], ah[s], bhp);   // hi*hi
                MMA16816(acc[tn], ah[s], blp);   // hi*lo
                MMA16816(acc[tn], al[s], bhp);   // lo*hi
            }
    }

    // epilogue: log + bias
    const int er = lane >> 2;
    const int ec = (lane & 3) * 2;
#pragma unroll
    for (int tn = 0; tn < TNC; tn++) {
        const int row = bm + wm + er;
        const int col = bn + wn + tn * 8 + ec;
        float2 o0, o1;
        o0.x = logf(acc[tn][0]) + bias[col];
        o0.y = logf(acc[tn][1]) + bias[col + 1];
        o1.x = logf(acc[tn][2]) + bias[col];
        o1.y = logf(acc[tn][3]) + bias[col + 1];
        *reinterpret_cast<float2*>(C + (size_t)row * OUT + col) = o0;
        *reinterpret_cast<float2*>(C + (size_t)(row + 8) * OUT + col) = o1;
    }
}

// ---------------------------------------------------------------------------
// trop_layernorm (median/IQR hybrid bitonic) + relu + exp + bf16 hi/lo split.
// ---------------------------------------------------------------------------
__global__ __launch_bounds__(256) void ln_kernel(
    const float* __restrict__ H, const float* __restrict__ w,
    const float* __restrict__ b,
    __nv_bfloat16* __restrict__ Oh, __nv_bfloat16* __restrict__ Ol) {
    __shared__ float s[512];
    const int row = blockIdx.x;
    const int t = threadIdx.x;
    const float* Hrow = H + row * 512;

    const float h0 = Hrow[t];
    const float h1 = Hrow[t + 256];
    float v0 = h0, v1 = h1;

#pragma unroll
    for (int k = 2; k <= 512; k <<= 1) {
        if (k == 512) {
            float m = fminf(v0, v1), M = fmaxf(v0, v1);
            v0 = m; v1 = M;
        }
#pragma unroll
        for (int j = (k >> 1) > 128 ? 128 : (k >> 1); j >= 32; j >>= 1) {
            __syncthreads();
            s[t] = v0; s[t + 256] = v1;
            __syncthreads();
            float p0 = s[t ^ j];
            float p1 = s[(t ^ j) + 256];
            bool asc0 = ((t & k) == 0);
            bool asc1 = (((t + 256) & k) == 0);
            bool low = ((t & j) == 0);
            v0 = (low == asc0) ? fminf(v0, p0) : fmaxf(v0, p0);
            v1 = (low == asc1) ? fminf(v1, p1) : fmaxf(v1, p1);
        }
#pragma unroll
        for (int j = (k >> 1) > 16 ? 16 : (k >> 1); j >= 1; j >>= 1) {
            bool asc0 = ((t & k) == 0);
            bool asc1 = (((t + 256) & k) == 0);
            bool low = ((t & j) == 0);
            float p0 = __shfl_xor_sync(0xffffffffu, v0, j);
            float p1 = __shfl_xor_sync(0xffffffffu, v1, j);
            v0 = (low == asc0) ? fminf(v0, p0) : fmaxf(v0, p0);
            v1 = (low == asc1) ? fminf(v1, p1) : fmaxf(v1, p1);
        }
    }

    __syncthreads();
    if (t == 127) { s[0] = v0; s[3] = v1; }
    if (t == 128) { s[1] = v0; s[4] = v1; }
    if (t == 255) { s[2] = v0; }
    __syncthreads();
    const float q25 = s[0] + 0.75f * (s[1] - s[0]);
    const float med = s[2];
    const float q75 = s[3] + 0.25f * (s[4] - s[3]);
    const float inv = 1.0f / fmaxf(q75 - q25, 1e-6f);

#pragma unroll
    for (int half = 0; half < 2; half++) {
        const int idx = t + half * 256;
        const float h = half ? h1 : h0;
        float o = fmaxf((h - med) * inv * w[idx] + b[idx], 0.0f);
        float e = expf(o);
        __nv_bfloat16 hi = __float2bfloat16(e);
        __nv_bfloat16 lo = __float2bfloat16(e - __bfloat162float(hi));
        Oh[row * 512 + idx] = hi;
        Ol[row * 512 + idx] = lo;
    }
}

// ---------------------------------------------------------------------------
extern "C" void kernel_launch(void* const* d_in, const int* in_sizes, int n_in,
                              void* d_out, int out_size) {
    const float* x    = (const float*)d_in[0];
    const float* w1   = (const float*)d_in[1];
    const float* b1   = (const float*)d_in[2];
    const float* ln1w = (const float*)d_in[3];
    const float* ln1b = (const float*)d_in[4];
    const float* w2   = (const float*)d_in[5];
    const float* b2   = (const float*)d_in[6];
    const float* ln2w = (const float*)d_in[7];
    const float* ln2b = (const float*)d_in[8];
    const float* w3   = (const float*)d_in[9];
    const float* b3   = (const float*)d_in[10];

    float* H;
    __nv_bfloat16 *Ah, *Al, *W1h, *W1l, *W2h, *W2l, *W3h, *W3l;
    cudaGetSymbolAddress((void**)&H, g_H);
    cudaGetSymbolAddress((void**)&Ah, g_Ah);
    cudaGetSymbolAddress((void**)&Al, g_Al);
    cudaGetSymbolAddress((void**)&W1h, g_W1h);
    cudaGetSymbolAddress((void**)&W1l, g_W1l);
    cudaGetSymbolAddress((void**)&W2h, g_W2h);
    cudaGetSymbolAddress((void**)&W2l, g_W2l);
    cudaGetSymbolAddress((void**)&W3h, g_W3h);
    cudaGetSymbolAddress((void**)&W3l, g_W3l);

    exp_split_kernel<<<1152, 256>>>(x, Ah, Al, w1, W1h, W1l, w2, W2h, W2l,
                                    w3, W3h, W3l);

    dim3 g12(512 / 64, 1024 / 64);   // 8 x 16 = 128 CTAs
    dim3 g3(256 / 64, 1024 / 32);    // 4 x 32 = 128 CTAs

    gemm_mma<64, 32><<<g12, 256>>>(Ah, Al, W1h, W1l, b1, H, 512);
    ln_kernel<<<1024, 256>>>(H, ln1w, ln1b, Ah, Al);
    gemm_mma<64, 32><<<g12, 256>>>(Ah, Al, W2h, W2l, b2, H, 512);
    ln_kernel<<<1024, 256>>>(H, ln2w, ln2b, Ah, Al);
    gemm_mma<32, 16><<<g3, 256>>>(Ah, Al, W3h, W3l, b3, (float*)d_out, 256);
}